// round 12
// baseline (speedup 1.0000x reference)
#include <cuda_runtime.h>
#include <cuda_bf16.h>

typedef unsigned int u32;

#define BB 64
#define TT 1024
#define DD 128
#define QT 32
#define KT 64
#define SCALE 0.08838834764831845f
#define LOG2E 1.4426950408889634f
#define MASK_FILL_L2 (-6.0e9f)

// 256B-row tiles: 16B unit `unit` of row `row`
#define SWZ_UNIT(row, unit) ((u32)(row) * 256u + (((u32)(unit) ^ ((u32)(row) & 7u)) << 4))

// ---- precomputed bf16 hi/lo operand images ----
__device__ __align__(16) unsigned char g_QHI[1 << 24];
__device__ __align__(16) unsigned char g_QLO[1 << 24];
__device__ __align__(16) unsigned char g_KHI[1 << 24];
__device__ __align__(16) unsigned char g_KLO[1 << 24];
__device__ __align__(16) unsigned char g_VHI[1 << 24];
__device__ __align__(16) unsigned char g_VLO[1 << 24];
// ---- per-row softmax stats (A -> B) ----
__device__ float g_M[BB * TT];
__device__ float g_L[BB * TT];

// ================= PTX helpers =================
__device__ __forceinline__ u32 smem_u32(const void* p) {
    u32 a;
    asm("{ .reg .u64 t; cvta.to.shared.u64 t, %1; cvt.u32.u64 %0, t; }" : "=r"(a) : "l"(p));
    return a;
}
__device__ __forceinline__ void cp16(u32 dst, const void* src) {
    asm volatile("cp.async.cg.shared.global [%0], [%1], 16;" :: "r"(dst), "l"(src));
}
#define CP_COMMIT() asm volatile("cp.async.commit_group;" ::: "memory")
#define CP_WAIT_ALL() asm volatile("cp.async.wait_group 0;" ::: "memory")

__device__ __forceinline__ void ldm_x4(u32* r, u32 addr) {
    asm volatile("ldmatrix.sync.aligned.m8n8.x4.shared.b16 {%0,%1,%2,%3}, [%4];"
                 : "=r"(r[0]), "=r"(r[1]), "=r"(r[2]), "=r"(r[3]) : "r"(addr));
}
__device__ __forceinline__ void ldm_x4t(u32* r, u32 addr) {
    asm volatile("ldmatrix.sync.aligned.m8n8.x4.trans.shared.b16 {%0,%1,%2,%3}, [%4];"
                 : "=r"(r[0]), "=r"(r[1]), "=r"(r[2]), "=r"(r[3]) : "r"(addr));
}
__device__ __forceinline__ void mma16816(float* c, const u32* a, const u32* b) {
    asm volatile(
        "mma.sync.aligned.m16n8k16.row.col.f32.bf16.bf16.f32 "
        "{%0,%1,%2,%3}, {%4,%5,%6,%7}, {%8,%9}, {%0,%1,%2,%3};"
        : "+f"(c[0]), "+f"(c[1]), "+f"(c[2]), "+f"(c[3])
        : "r"(a[0]), "r"(a[1]), "r"(a[2]), "r"(a[3]), "r"(b[0]), "r"(b[1]));
}
__device__ __forceinline__ void cvt_split2(float x0, float x1, u32& hi, u32& lo) {
    __nv_bfloat16 h0 = __float2bfloat16(x0);
    __nv_bfloat16 h1 = __float2bfloat16(x1);
    __nv_bfloat16 l0 = __float2bfloat16(x0 - __bfloat162float(h0));
    __nv_bfloat16 l1 = __float2bfloat16(x1 - __bfloat162float(h1));
    __nv_bfloat162 H(h0, h1), L(l0, l1);
    hi = *reinterpret_cast<u32*>(&H);
    lo = *reinterpret_cast<u32*>(&L);
}
__device__ __forceinline__ float exp2_mufu(float v) {
    float r;
    asm("ex2.approx.f32 %0, %1;" : "=f"(r) : "f"(v));
    return r;
}

// ---------------- mask dtype mode ----------------
__device__ int g_mask_mode;   // 0=u8, 1=i32, 2=f32

// ---------------- prep: f32 -> bf16 hi/lo swizzled tile images (+ mask probe) ----------------
__global__ __launch_bounds__(512)
void prep_kernel(const float* __restrict__ query,
                 const float* __restrict__ key,
                 const float* __restrict__ value,
                 const unsigned char* __restrict__ mask)
{
    if (blockIdx.x == 6144) {   // probe block (warp 0 only)
        if (threadIdx.x >= 32) return;
        const int lane = threadIdx.x;
        const float* mf = (const float*)mask;
        bool f01 = true;
        for (int i = lane; i < 1024; i += 32) {
            float f = mf[i];
            if (f != 0.0f && f != 1.0f) f01 = false;
        }
        if (__all_sync(0xffffffffu, f01)) {
            if (lane == 0) g_mask_mode = 2;
            return;
        }
        u32 any_high = 0;
        for (int i = lane * 4; i < 4096; i += 128)
            any_high |= (mask[i + 1] | mask[i + 2] | mask[i + 3]);
        int any = __any_sync(0xffffffffu, any_high != 0);
        if (lane == 0) g_mask_mode = any ? 0 : 1;
        return;
    }

    int idx = blockIdx.x * blockDim.x + threadIdx.x;
    int tensor = idx >> 20;
    int u = idx & 1048575;
    int unit = u & 15;
    int seq = (u >> 4) & 1023;
    int b = u >> 14;

    const float* src;
    unsigned char *dhi, *dlo;
    float scale = 1.0f;
    size_t img;
    int r;
    if (tensor == 0) {
        src = query; dhi = g_QHI; dlo = g_QLO; scale = SCALE * LOG2E;
        img = (size_t)(b * 32 + (seq >> 5)) << 13; r = seq & 31;   // 32-row Q tiles
    } else if (tensor == 1) {
        src = key; dhi = g_KHI; dlo = g_KLO;
        img = (size_t)(b * 16 + (seq >> 6)) << 14; r = seq & 63;
    } else {
        src = value; dhi = g_VHI; dlo = g_VLO;
        img = (size_t)(b * 16 + (seq >> 6)) << 14; r = seq & 63;
    }
    const float4* s4 = (const float4*)(src + ((size_t)b * TT + seq) * DD + unit * 8);
    float4 x0 = s4[0], x1 = s4[1];
    uint4 H, L;
    cvt_split2(x0.x * scale, x0.y * scale, H.x, L.x);
    cvt_split2(x0.z * scale, x0.w * scale, H.y, L.y);
    cvt_split2(x1.x * scale, x1.y * scale, H.z, L.z);
    cvt_split2(x1.z * scale, x1.w * scale, H.w, L.w);
    u32 off = (u32)r * 256u + (((u32)(unit ^ (r & 7))) << 4);
    *(uint4*)(dhi + img + off) = H;
    *(uint4*)(dlo + img + off) = L;
}

// =====================================================================
// Kernel A: scores = (Q*scale*log2e) @ K^T, masked, -> gmem (raw, log2 domain)
//           + per-row online (max, sumexp) -> g_M / g_L
// =====================================================================
#define A_THREADS 256
#define A_SMQ   0            // Q hi 8KB | lo 8KB
#define A_SMK   16384        // K hi 16KB | lo 16KB
#define A_SMRED 49152        // 32 rows x 4 x float2 = 1KB
#define A_SMEM  50176

__global__ __launch_bounds__(A_THREADS, 4)
void qk_kernel(const void* __restrict__ mask,
               float* __restrict__ scores)       // [B,T,T] scratch (= attn buffer)
{
    extern __shared__ char smem[];
    const u32 sb = smem_u32(smem);
    float2* sred = (float2*)(smem + A_SMRED);

    const int b    = blockIdx.x >> 5;
    const int q0   = (blockIdx.x & 31) * QT;
    const int tid  = threadIdx.x;
    const int wid  = tid >> 5;        // 0..7
    const int lane = tid & 31;
    const int grp  = lane >> 3;
    const int sub  = lane & 7;
    const int g    = lane >> 2;
    const int t    = lane & 3;
    const int wm   = wid & 1;
    const int wn   = wid >> 1;        // 0..3
    const int n0   = wn * 16;
    const int mmode = g_mask_mode;

    // preload Q image (hi 8KB + lo 8KB)
    {
        size_t qimg = (size_t)(b * 32 + (q0 >> 5)) << 13;
        #pragma unroll
        for (int i = 0; i < 2; ++i) {
            int c = tid + i * 256;
            cp16(sb + A_SMQ + c * 16, g_QHI + qimg + (size_t)c * 16);
            cp16(sb + A_SMQ + 8192 + c * 16, g_QLO + qimg + (size_t)c * 16);
        }
        CP_COMMIT();
    }

    const int rowA = wm * 16 + sub + ((grp & 1) << 3);
    const u32 hilo = (grp >> 1) ? 16384u : 0u;
    const int r0 = wm * 16 + g;          // this thread's rows
    const int r1 = r0 + 8;
    const size_t mbase = (size_t)b * TT * TT + (size_t)q0 * TT;
    float m0 = -3.402823466e38f, l0 = 0.f;
    float m1 = -3.402823466e38f, l1 = 0.f;

    for (int kt = 0; kt < TT / KT; ++kt) {
        if (kt) __syncthreads();         // K buffer consumed
        {
            size_t kbase = (size_t)(b * 16 + kt) << 14;
            #pragma unroll
            for (int i = 0; i < 4; ++i) {
                int c = tid + i * 256;
                cp16(sb + A_SMK + c * 16, g_KHI + kbase + (size_t)c * 16);
                cp16(sb + A_SMK + 16384 + c * 16, g_KLO + kbase + (size_t)c * 16);
            }
            CP_COMMIT();
            CP_WAIT_ALL();
        }
        __syncthreads();

        float ahh[2][4] = {{0,0,0,0},{0,0,0,0}};
        float ahl[2][4] = {{0,0,0,0},{0,0,0,0}};
        float alh[2][4] = {{0,0,0,0},{0,0,0,0}};
        #pragma unroll
        for (int ks = 0; ks < 8; ++ks) {
            u32 qoff = SWZ_UNIT(rowA, 2 * ks + (grp >> 1));
            u32 qh[4], ql[4];
            ldm_x4(qh, sb + A_SMQ + qoff);
            ldm_x4(ql, sb + A_SMQ + 8192 + qoff);
            #pragma unroll
            for (int nt = 0; nt < 2; ++nt) {
                u32 bb[4];
                ldm_x4(bb, sb + A_SMK + hilo + SWZ_UNIT(n0 + nt * 8 + sub, 2 * ks + (grp & 1)));
                mma16816(ahh[nt], qh, bb);
                mma16816(ahl[nt], qh, bb + 2);
                mma16816(alh[nt], ql, bb);
            }
        }

        // epilogue: mask + STG raw scores + online (m,l)
        float sr0[4], sr1[4];
        #pragma unroll
        for (int nt = 0; nt < 2; ++nt) {
            int col = kt * KT + n0 + nt * 8 + 2 * t;
            float s0 = ahh[nt][0] + ahl[nt][0] + alh[nt][0];
            float s1 = ahh[nt][1] + ahl[nt][1] + alh[nt][1];
            float s2 = ahh[nt][2] + ahl[nt][2] + alh[nt][2];
            float s3 = ahh[nt][3] + ahl[nt][3] + alh[nt][3];
            bool k00, k01, k10, k11;
            if (mmode == 0) {
                const unsigned char* mp0 = (const unsigned char*)mask + mbase + (size_t)r0 * TT + col;
                const unsigned char* mp1 = (const unsigned char*)mask + mbase + (size_t)r1 * TT + col;
                k00 = mp0[0] != 0; k01 = mp0[1] != 0;
                k10 = mp1[0] != 0; k11 = mp1[1] != 0;
            } else if (mmode == 1) {
                int2 v0 = *(const int2*)((const int*)mask + mbase + (size_t)r0 * TT + col);
                int2 v1 = *(const int2*)((const int*)mask + mbase + (size_t)r1 * TT + col);
                k00 = v0.x != 0; k01 = v0.y != 0;
                k10 = v1.x != 0; k11 = v1.y != 0;
            } else {
                float2 v0 = *(const float2*)((const float*)mask + mbase + (size_t)r0 * TT + col);
                float2 v1 = *(const float2*)((const float*)mask + mbase + (size_t)r1 * TT + col);
                k00 = v0.x != 0.0f; k01 = v0.y != 0.0f;
                k10 = v1.x != 0.0f; k11 = v1.y != 0.0f;
            }
            if (k00) s0 = MASK_FILL_L2;
            if (k01) s1 = MASK_FILL_L2;
            if (k10) s2 = MASK_FILL_L2;
            if (k11) s3 = MASK_FILL_L2;
            *(float2*)(scores + ((size_t)b * TT + q0 + r0) * TT + col) = make_float2(s0, s1);
            *(float2*)(scores + ((size_t)b * TT + q0 + r1) * TT + col) = make_float2(s2, s3);
            sr0[2 * nt] = s0; sr0[2 * nt + 1] = s1;
            sr1[2 * nt] = s2; sr1[2 * nt + 1] = s3;
        }
        // online update row r0
        {
            float bm = fmaxf(fmaxf(sr0[0], sr0[1]), fmaxf(sr0[2], sr0[3]));
            float nm = fmaxf(m0, bm);
            l0 = l0 * exp2_mufu(m0 - nm)
               + exp2_mufu(sr0[0] - nm) + exp2_mufu(sr0[1] - nm)
               + exp2_mufu(sr0[2] - nm) + exp2_mufu(sr0[3] - nm);
            m0 = nm;
        }
        // online update row r1
        {
            float bm = fmaxf(fmaxf(sr1[0], sr1[1]), fmaxf(sr1[2], sr1[3]));
            float nm = fmaxf(m1, bm);
            l1 = l1 * exp2_mufu(m1 - nm)
               + exp2_mufu(sr1[0] - nm) + exp2_mufu(sr1[1] - nm)
               + exp2_mufu(sr1[2] - nm) + exp2_mufu(sr1[3] - nm);
            m1 = nm;
        }
    }

    // quad reduce (lanes t=0..3 share a row)
    #pragma unroll
    for (int o = 1; o <= 2; o <<= 1) {
        float om = __shfl_xor_sync(0xffffffffu, m0, o);
        float ol = __shfl_xor_sync(0xffffffffu, l0, o);
        float nm = fmaxf(m0, om);
        l0 = l0 * exp2_mufu(m0 - nm) + ol * exp2_mufu(om - nm);
        m0 = nm;
        om = __shfl_xor_sync(0xffffffffu, m1, o);
        ol = __shfl_xor_sync(0xffffffffu, l1, o);
        nm = fmaxf(m1, om);
        l1 = l1 * exp2_mufu(m1 - nm) + ol * exp2_mufu(om - nm);
        m1 = nm;
    }
    if (t == 0) {
        sred[r0 * 4 + wn] = make_float2(m0, l0);
        sred[r1 * 4 + wn] = make_float2(m1, l1);
    }
    __syncthreads();
    if (tid < 32) {
        float2 a0 = sred[tid * 4 + 0], a1 = sred[tid * 4 + 1];
        float2 a2 = sred[tid * 4 + 2], a3 = sred[tid * 4 + 3];
        float mm = fmaxf(fmaxf(a0.x, a1.x), fmaxf(a2.x, a3.x));
        float ll = a0.y * exp2_mufu(a0.x - mm) + a1.y * exp2_mufu(a1.x - mm)
                 + a2.y * exp2_mufu(a2.x - mm) + a3.y * exp2_mufu(a3.x - mm);
        g_M[(size_t)b * TT + q0 + tid] = mm;
        g_L[(size_t)b * TT + q0 + tid] = ll;
    }
}

// =====================================================================
// Kernel B: attn = exp2(s - m) * qmask/l  (write final attn) ; out = attn @ V
// =====================================================================
#define B_THREADS 512
#define B_SMS    0            // score stages: 2 x 8KB
#define B_SMV    16384        // V hi 16KB | lo 16KB
#define B_SMP    49152        // P planes: hi 4608 | lo 4608 (stride 144)
#define B_SMSTAT 58368        // m[32], inv[32]
#define B_SMEM   58624

__global__ __launch_bounds__(B_THREADS, 2)
void pv_kernel(const float* __restrict__ qmask,
               float* __restrict__ attn,          // in: raw scores, out: final attn
               float* __restrict__ out_res)
{
    extern __shared__ char smem[];
    const u32 sb = smem_u32(smem);
    float* sstat = (float*)(smem + B_SMSTAT);

    const int b    = blockIdx.x >> 5;
    const int q0   = (blockIdx.x & 31) * QT;
    const int tid  = threadIdx.x;
    const int wid  = tid >> 5;        // 0..15
    const int lane = tid & 31;
    const int grp  = lane >> 3;
    const int sub  = lane & 7;
    const int g    = lane >> 2;
    const int t    = lane & 3;
    const int wm   = wid & 1;
    const int wn   = wid >> 1;        // 0..7

    // stats
    if (tid < 32) {
        float m = g_M[(size_t)b * TT + q0 + tid];
        float l = g_L[(size_t)b * TT + q0 + tid];
        sstat[tid] = m;
        sstat[32 + tid] = qmask[(size_t)b * TT + q0 + tid] / l;
    }

    float* sc_base = attn + ((size_t)b * TT + q0) * TT;

    // prologue: scores(0) + V(0)
    {
        int c = tid;  // 512 units of 16B = 8KB score tile
        int row = c >> 4, seg = c & 15;
        cp16(sb + B_SMS + c * 16, sc_base + (size_t)row * TT + seg * 4);
        size_t vbase = (size_t)(b * 16) << 14;
        #pragma unroll
        for (int i = 0; i < 2; ++i) {
            int cc = tid + i * 512;
            cp16(sb + B_SMV + cc * 16, g_VHI + vbase + (size_t)cc * 16);
            cp16(sb + B_SMV + 16384 + cc * 16, g_VLO + vbase + (size_t)cc * 16);
        }
        CP_COMMIT();
    }

    float rhh[2][4] = {{0,0,0,0},{0,0,0,0}};
    float rhl[2][4] = {{0,0,0,0},{0,0,0,0}};
    float rlh[2][4] = {{0,0,0,0},{0,0,0,0}};

    const int crow = tid >> 4;            // convert row 0..31
    const int cp0  = tid & 15;
    const int rowA = wm * 16 + sub + ((grp & 1) << 3);
    const int rowB0 = sub + ((grp & 1) << 3);
    const int unitB = 2 * wn + (grp >> 1);
    const u32 prx = (u32)(rowA & 7);

    for (int kt = 0; kt < TT / KT; ++kt) {
        CP_WAIT_ALL();
        __syncthreads();
        if (kt < 15) {   // prefetch next score tile into other stage
            int c = tid, row = c >> 4, seg = c & 15;
            cp16(sb + B_SMS + ((kt + 1) & 1) * 8192 + c * 16,
                 sc_base + (size_t)row * TT + (kt + 1) * KT + seg * 4);
            CP_COMMIT();
        }
        // convert: exp2, write final attn, split to P planes
        {
            const u32 st = sb + B_SMS + (kt & 1) * 8192;
            float m = sstat[crow], inv = sstat[32 + crow];
            #pragma unroll
            for (int j = 0; j < 2; ++j) {
                int p = cp0 + 16 * j;
                float2 s;
                asm volatile("ld.shared.v2.f32 {%0,%1}, [%2];"
                             : "=f"(s.x), "=f"(s.y) : "r"(st + crow * 256 + p * 8));
                float e0 = exp2_mufu(s.x - m) * inv;
                float e1 = exp2_mufu(s.y - m) * inv;
                *(float2*)(sc_base + (size_t)crow * TT + kt * KT + 2 * p) = make_float2(e0, e1);
                u32 hi, lo;
                cvt_split2(e0, e1, hi, lo);
                u32 off = (u32)crow * 144u + (((u32)(p >> 2) ^ ((u32)crow & 7u)) << 4) + ((u32)(p & 3) << 2);
                *(u32*)(smem + B_SMP + off) = hi;
                *(u32*)(smem + B_SMP + 4608 + off) = lo;
            }
        }
        __syncthreads();
        // MMA: P(kt) x V(kt)
        #pragma unroll
        for (int ks = 0; ks < 4; ++ks) {
            u32 U = (u32)(2 * ks + (grp >> 1));
            u32 offA = (u32)rowA * 144u + ((U ^ prx) << 4);
            u32 ah[4], al[4];
            ldm_x4(ah, sb + B_SMP + offA);
            ldm_x4(al, sb + B_SMP + 4608 + offA);
            u32 offB = SWZ_UNIT(ks * 16 + rowB0, unitB);
            u32 bh[4], bl[4];
            ldm_x4t(bh, sb + B_SMV + offB);
            ldm_x4t(bl, sb + B_SMV + 16384 + offB);
            #pragma unroll
            for (int tile = 0; tile < 2; ++tile) {
                mma16816(rhh[tile], ah, bh + 2 * tile);
                mma16816(rhl[tile], ah, bl + 2 * tile);
                mma16816(rlh[tile], al, bh + 2 * tile);
            }
        }
        __syncthreads();   // V consumed
        if (kt < 15) {     // next V tile
            size_t vbase = (size_t)(b * 16 + kt + 1) << 14;
            #pragma unroll
            for (int i = 0; i < 2; ++i) {
                int cc = tid + i * 512;
                cp16(sb + B_SMV + cc * 16, g_VHI + vbase + (size_t)cc * 16);
                cp16(sb + B_SMV + 16384 + cc * 16, g_VLO + vbase + (size_t)cc * 16);
            }
            CP_COMMIT();
        }
    }

    // epilogue
    #pragma unroll
    for (int tile = 0; tile < 2; ++tile) {
        int col = wn * 16 + tile * 8 + 2 * t;
        int row = q0 + wm * 16 + g;
        *(float2*)&out_res[((size_t)b * TT + row) * DD + col] =
            make_float2(rhh[tile][0] + rhl[tile][0] + rlh[tile][0],
                        rhh[tile][1] + rhl[tile][1] + rlh[tile][1]);
        *(float2*)&out_res[((size_t)b * TT + row + 8) * DD + col] =
            make_float2(rhh[tile][2] + rhl[tile][2] + rlh[tile][2],
                        rhh[tile][3] + rhl[tile][3] + rlh[tile][3]);
    }
}

extern "C" void kernel_launch(void* const* d_in, const int* in_sizes, int n_in,
                              void* d_out, int out_size) {
    const float* key   = (const float*)d_in[0];
    const float* value = (const float*)d_in[1];
    const float* query = (const float*)d_in[2];
    const void*  mask  = d_in[3];
    const float* qmask = (const float*)d_in[4];

    float* out      = (float*)d_out;
    float* out_res  = out;                          // [B, T, D] first (tuple order)
    float* out_attn = out + (size_t)BB * TT * DD;   // [B, T, T] second

    prep_kernel<<<6145, 512>>>(query, key, value, (const unsigned char*)mask);

    cudaFuncSetAttribute(qk_kernel, cudaFuncAttributeMaxDynamicSharedMemorySize, A_SMEM);
    cudaFuncSetAttribute(pv_kernel, cudaFuncAttributeMaxDynamicSharedMemorySize, B_SMEM);

    dim3 grid(BB * (TT / QT));   // 2048 CTAs each
    qk_kernel<<<grid, A_THREADS, A_SMEM>>>(mask, out_attn);
    pv_kernel<<<grid, B_THREADS, B_SMEM>>>(qmask, out_attn, out_res);
}

// round 14
// speedup vs baseline: 1.6194x; 1.6194x over previous
#include <cuda_runtime.h>
#include <cuda_bf16.h>

typedef unsigned int u32;

#define BB 64
#define TT 1024
#define DD 128
#define QT 32                  // q rows per CTA
#define KT 64                  // k-seq tile
#define NTILES (TT/KT)         // 16
#define NTHREADS 512
#define SSTRIDE 1032
#define ROWB (SSTRIDE*4)       // 4128 bytes per score row
#define SCALE 0.08838834764831845f
#define LOG2E 1.4426950408889634f
#define MASK_FILL_L2 (-6.0e9f)

// ---- smem layout (bytes) ----
#define SM_SS    0                          // 32 x 1032 f32 scores (132096)
                                            // phase>=2: per-row bf16 P hi [0,2048) lo [2048,4096)
#define SM_ST    132096                     // 3 stages x {hi 16KB, lo 16KB} = 98304
#define SM_TOTAL (SM_ST + 3*32768)          // 230400 (Q image borrows stage 2 in prologue)

// 256B-row tiles: 16B unit `unit` of row `row`
#define SWZ_UNIT(row, unit) ((u32)(row) * 256u + (((u32)(unit) ^ ((u32)(row) & 7u)) << 4))

// ---- precomputed bf16 hi/lo operand images ----
__device__ __align__(16) unsigned char g_QHI[1 << 24];
__device__ __align__(16) unsigned char g_QLO[1 << 24];
__device__ __align__(16) unsigned char g_KHI[1 << 24];
__device__ __align__(16) unsigned char g_KLO[1 << 24];
__device__ __align__(16) unsigned char g_VHI[1 << 24];
__device__ __align__(16) unsigned char g_VLO[1 << 24];

// ================= PTX helpers =================
__device__ __forceinline__ u32 smem_u32(const void* p) {
    u32 a;
    asm("{ .reg .u64 t; cvta.to.shared.u64 t, %1; cvt.u32.u64 %0, t; }" : "=r"(a) : "l"(p));
    return a;
}
__device__ __forceinline__ void cp16(u32 dst, const void* src) {
    asm volatile("cp.async.cg.shared.global [%0], [%1], 16;" :: "r"(dst), "l"(src));
}
#define CP_COMMIT()  asm volatile("cp.async.commit_group;" ::: "memory")
#define CP_WAIT1()   asm volatile("cp.async.wait_group 1;" ::: "memory")
#define CP_WAIT_ALL() asm volatile("cp.async.wait_group 0;" ::: "memory")

__device__ __forceinline__ void ldm_x4(u32* r, u32 addr) {
    asm volatile("ldmatrix.sync.aligned.m8n8.x4.shared.b16 {%0,%1,%2,%3}, [%4];"
                 : "=r"(r[0]), "=r"(r[1]), "=r"(r[2]), "=r"(r[3]) : "r"(addr));
}
__device__ __forceinline__ void ldm_x4t(u32* r, u32 addr) {
    asm volatile("ldmatrix.sync.aligned.m8n8.x4.trans.shared.b16 {%0,%1,%2,%3}, [%4];"
                 : "=r"(r[0]), "=r"(r[1]), "=r"(r[2]), "=r"(r[3]) : "r"(addr));
}
__device__ __forceinline__ void mma16816(float* c, const u32* a, const u32* b) {
    asm volatile(
        "mma.sync.aligned.m16n8k16.row.col.f32.bf16.bf16.f32 "
        "{%0,%1,%2,%3}, {%4,%5,%6,%7}, {%8,%9}, {%0,%1,%2,%3};"
        : "+f"(c[0]), "+f"(c[1]), "+f"(c[2]), "+f"(c[3])
        : "r"(a[0]), "r"(a[1]), "r"(a[2]), "r"(a[3]), "r"(b[0]), "r"(b[1]));
}
__device__ __forceinline__ void cvt_split2(float x0, float x1, u32& hi, u32& lo) {
    __nv_bfloat16 h0 = __float2bfloat16(x0);
    __nv_bfloat16 h1 = __float2bfloat16(x1);
    __nv_bfloat16 l0 = __float2bfloat16(x0 - __bfloat162float(h0));
    __nv_bfloat16 l1 = __float2bfloat16(x1 - __bfloat162float(h1));
    __nv_bfloat162 H(h0, h1), L(l0, l1);
    hi = *reinterpret_cast<u32*>(&H);
    lo = *reinterpret_cast<u32*>(&L);
}
__device__ __forceinline__ float exp2_mufu(float v) {
    float r;
    asm("ex2.approx.f32 %0, %1;" : "=f"(r) : "f"(v));
    return r;
}

// ---------------- mask dtype mode ----------------
__device__ int g_mask_mode;   // 0=u8, 1=i32, 2=f32

// ---------------- prep: f32 -> bf16 hi/lo swizzled tile images (+ mask probe) ----------------
__global__ __launch_bounds__(512)
void prep_kernel(const float* __restrict__ query,
                 const float* __restrict__ key,
                 const float* __restrict__ value,
                 const unsigned char* __restrict__ mask)
{
    if (blockIdx.x == 6144) {   // probe block (warp 0 only)
        if (threadIdx.x >= 32) return;
        const int lane = threadIdx.x;
        const float* mf = (const float*)mask;
        bool f01 = true;
        for (int i = lane; i < 1024; i += 32) {
            float f = mf[i];
            if (f != 0.0f && f != 1.0f) f01 = false;
        }
        if (__all_sync(0xffffffffu, f01)) {
            if (lane == 0) g_mask_mode = 2;
            return;
        }
        u32 any_high = 0;
        for (int i = lane * 4; i < 4096; i += 128)
            any_high |= (mask[i + 1] | mask[i + 2] | mask[i + 3]);
        int any = __any_sync(0xffffffffu, any_high != 0);
        if (lane == 0) g_mask_mode = any ? 0 : 1;
        return;
    }

    int idx = blockIdx.x * blockDim.x + threadIdx.x;
    int tensor = idx >> 20;
    int u = idx & 1048575;
    int unit = u & 15;
    int seq = (u >> 4) & 1023;
    int b = u >> 14;

    const float* src;
    unsigned char *dhi, *dlo;
    float scale = 1.0f;
    size_t img;
    int r;
    if (tensor == 0) {
        src = query; dhi = g_QHI; dlo = g_QLO; scale = SCALE * LOG2E;
        img = (size_t)(b * 32 + (seq >> 5)) << 13; r = seq & 31;
    } else if (tensor == 1) {
        src = key; dhi = g_KHI; dlo = g_KLO;
        img = (size_t)(b * 16 + (seq >> 6)) << 14; r = seq & 63;
    } else {
        src = value; dhi = g_VHI; dlo = g_VLO;
        img = (size_t)(b * 16 + (seq >> 6)) << 14; r = seq & 63;
    }
    const float4* s4 = (const float4*)(src + ((size_t)b * TT + seq) * DD + unit * 8);
    float4 x0 = s4[0], x1 = s4[1];
    uint4 H, L;
    cvt_split2(x0.x * scale, x0.y * scale, H.x, L.x);
    cvt_split2(x0.z * scale, x0.w * scale, H.y, L.y);
    cvt_split2(x1.x * scale, x1.y * scale, H.z, L.z);
    cvt_split2(x1.z * scale, x1.w * scale, H.w, L.w);
    u32 off = (u32)r * 256u + (((u32)(unit ^ (r & 7))) << 4);
    *(uint4*)(dhi + img + off) = H;
    *(uint4*)(dlo + img + off) = L;
}

// ---------------- KV tile copy (64 rows x 256B, hi+lo), 512 threads ----------------
__device__ __forceinline__ void copy_kv_tile(u32 dst, const unsigned char* ghi,
                                             const unsigned char* glo, size_t base, int tid)
{
    #pragma unroll
    for (int i = 0; i < 2; ++i) {
        int c = tid + i * 512;
        cp16(dst + c * 16, ghi + base + (size_t)c * 16);
        cp16(dst + 16384 + c * 16, glo + base + (size_t)c * 16);
    }
}

// ================= fused attention =================
__global__ __launch_bounds__(NTHREADS, 1)
void mh_attn_mma10_kernel(const void* __restrict__ mask,
                          const float* __restrict__ qmask,
                          float* __restrict__ out_res,
                          float* __restrict__ out_attn)
{
    extern __shared__ char smem[];
    float* sS = (float*)smem;
    const u32 sb = smem_u32(smem);

    const int b    = blockIdx.x >> 5;
    const int q0   = (blockIdx.x & 31) * QT;
    const int tid  = threadIdx.x;
    const int wid  = tid >> 5;
    const int lane = tid & 31;
    const int grp  = lane >> 3;
    const int sub  = lane & 7;
    const int g    = lane >> 2;
    const int t    = lane & 3;
    const int wm   = wid & 1;
    const int wn   = wid >> 1;      // 0..7
    const int m0   = wm * 16;

    const u32 st0 = sb + SM_ST;
    const u32 st1 = st0 + 32768;
    const u32 st2 = st0 + 65536;    // holds Q image during prologue

    // ---- prologue: Q -> stage2 + K0 -> stage0 (group 1); K1 -> stage1 (group 2) ----
    {
        size_t qimg = (size_t)(b * 32 + (q0 >> 5)) << 13;
        cp16(st2 + tid * 16, g_QHI + qimg + (size_t)tid * 16);
        cp16(st2 + 8192 + tid * 16, g_QLO + qimg + (size_t)tid * 16);
        copy_kv_tile(st0, g_KHI, g_KLO, (size_t)(b * 16) << 14, tid);
        CP_COMMIT();
        copy_kv_tile(st1, g_KHI, g_KLO, (size_t)(b * 16 + 1) << 14, tid);
        CP_COMMIT();
    }
    CP_WAIT1();          // Q + K0 landed (K1 may be in flight)
    __syncthreads();

    // ---- cache Q fragments (m16 x k128, hi+lo) from stage2 ----
    u32 qhi[8][4], qlo[8][4];
    {
        int rowA = m0 + sub + ((grp & 1) << 3);
        #pragma unroll
        for (int ks = 0; ks < 8; ++ks) {
            u32 off = SWZ_UNIT(rowA, 2 * ks + (grp >> 1));
            ldm_x4(qhi[ks], st2 + off);
            ldm_x4(qlo[ks], st2 + 8192 + off);
        }
    }

    // =========== Phase 1: S' = (Q*scale*log2e) @ K^T -> sS (f32) ===========
    // 3-stage pipeline: iter kt computes stage kt%3, issues K(kt+2) into (kt+2)%3.
    // Tail: at kt = NTILES-1, K(kt) is the LAST committed group -> full drain.
    {
        const int rowB = wn * 8 + sub;
        const u32 hilo = (grp >> 1) ? 16384u : 0u;
        for (int kt = 0; kt < NTILES; ++kt) {
            if (kt == NTILES - 1) CP_WAIT_ALL();
            else                  CP_WAIT1();      // copy(kt) complete
            __syncthreads();     // stage visible to all; stage (kt+2)%3 free
            const u32 stage = st0 + (u32)(kt % 3) * 32768 + hilo;
            float ahh[4] = {0.f,0.f,0.f,0.f};
            float ahl[4] = {0.f,0.f,0.f,0.f};
            float alh[4] = {0.f,0.f,0.f,0.f};
            #pragma unroll
            for (int ks = 0; ks < 8; ++ks) {
                u32 bb[4];   // bb[0..1]=bhi, bb[2..3]=blo (lane-mixed tiles)
                ldm_x4(bb, stage + SWZ_UNIT(rowB, 2 * ks + (grp & 1)));
                mma16816(ahh, qhi[ks], bb);
                mma16816(ahl, qhi[ks], bb + 2);
                mma16816(alh, qlo[ks], bb);
            }
            int col = kt * KT + wn * 8 + 2 * t;
            *(float2*)&sS[(m0 + g) * SSTRIDE + col] =
                make_float2(ahh[0] + ahl[0] + alh[0], ahh[1] + ahl[1] + alh[1]);
            *(float2*)&sS[(m0 + g + 8) * SSTRIDE + col] =
                make_float2(ahh[2] + ahl[2] + alh[2], ahh[3] + ahl[3] + alh[3]);
            if (kt + 2 < NTILES) {
                copy_kv_tile(st0 + (u32)((kt + 2) % 3) * 32768,
                             g_KHI, g_KLO, (size_t)(b * 16 + kt + 2) << 14, tid);
                CP_COMMIT();
            }
        }
    }
    __syncthreads();   // all phase-1 compute done; all K copies drained

    // ---- prefetch V0 -> stage0, V1 -> stage1 (land during softmax) ----
    copy_kv_tile(st0, g_VHI, g_VLO, (size_t)(b * 16) << 14, tid);
    CP_COMMIT();
    copy_kv_tile(st1, g_VHI, g_VLO, (size_t)(b * 16 + 1) << 14, tid);
    CP_COMMIT();

    // =========== Phase 2: softmax + in-place bf16 P conversion ===========
    {
        const int mmode = g_mask_mode;
        float* attn_g = out_attn + ((size_t)b * TT + q0) * TT;
        for (int r = wid; r < QT; r += 16) {
            char* rowb = smem + SM_SS + r * ROWB;
            const size_t mrow = (size_t)b * TT * TT + (size_t)(q0 + r) * TT;

            float2 sv[16];
            float mx = -3.402823466e38f;
            #pragma unroll
            for (int jj = 0; jj < 16; ++jj) {
                int c2 = lane + 32 * jj;            // element pair index
                float2 s2 = *(const float2*)(rowb + 8 * c2);
                bool k0, k1;
                if (mmode == 0) {
                    const unsigned char* mp = (const unsigned char*)mask + mrow + 2 * c2;
                    k0 = mp[0] != 0; k1 = mp[1] != 0;
                } else if (mmode == 1) {
                    int2 mv = *(const int2*)((const int*)mask + mrow + 2 * c2);
                    k0 = mv.x != 0; k1 = mv.y != 0;
                } else {
                    float2 mv = *(const float2*)((const float*)mask + mrow + 2 * c2);
                    k0 = mv.x != 0.0f; k1 = mv.y != 0.0f;
                }
                if (k0) s2.x = MASK_FILL_L2;
                if (k1) s2.y = MASK_FILL_L2;
                sv[jj] = s2;
                mx = fmaxf(mx, fmaxf(s2.x, s2.y));
            }
            #pragma unroll
            for (int o = 16; o; o >>= 1) mx = fmaxf(mx, __shfl_xor_sync(0xffffffffu, mx, o));

            float sum0 = 0.f, sum1 = 0.f;
            #pragma unroll
            for (int jj = 0; jj < 16; ++jj) {
                float e0 = exp2_mufu(sv[jj].x - mx);
                float e1 = exp2_mufu(sv[jj].y - mx);
                sv[jj].x = e0; sv[jj].y = e1;
                sum0 += e0; sum1 += e1;
            }
            float sum = sum0 + sum1;
            #pragma unroll
            for (int o = 16; o; o >>= 1) sum += __shfl_xor_sync(0xffffffffu, sum, o);
            float inv = qmask[(size_t)b * TT + q0 + r] / sum;

            __syncwarp();   // all f32 reads of this row complete before overwrite
            #pragma unroll
            for (int jj = 0; jj < 16; ++jj) {
                int c2 = lane + 32 * jj;
                float a0 = sv[jj].x * inv, a1 = sv[jj].y * inv;
                *(float2*)(attn_g + (size_t)r * TT + 2 * c2) = make_float2(a0, a1);
                u32 hi, lo;
                cvt_split2(a0, a1, hi, lo);
                u32 off = ((u32)((c2 >> 2) ^ (r & 7)) << 4) + ((u32)(c2 & 3) << 2);
                *(u32*)(rowb + off) = hi;
                *(u32*)(rowb + 2048 + off) = lo;
            }
        }
    }

    // =========== Phase 3: result = P @ V (P ldmatrix'd straight from sS) ===========
    float rhh[2][4] = {{0.f,0.f,0.f,0.f},{0.f,0.f,0.f,0.f}};
    float rhl[2][4] = {{0.f,0.f,0.f,0.f},{0.f,0.f,0.f,0.f}};
    float rlh[2][4] = {{0.f,0.f,0.f,0.f},{0.f,0.f,0.f,0.f}};
    {
        const int rowA  = m0 + sub + ((grp & 1) << 3);
        const int rowB0 = sub + ((grp & 1) << 3);
        const int unitB = 2 * wn + (grp >> 1);
        const u32 pbase = sb + SM_SS + (u32)rowA * ROWB;   // this lane's P row
        const u32 prx   = (u32)(rowA & 7);

        for (int kt = 0; kt < NTILES; ++kt) {
            if (kt == NTILES - 1) CP_WAIT_ALL();   // V(kt) is last committed group
            else                  CP_WAIT1();      // V(kt) complete
            __syncthreads();     // P planes + V stage visible; next stage free
            const u32 stV = st0 + (u32)(kt % 3) * 32768;
            #pragma unroll
            for (int ks = 0; ks < 4; ++ks) {
                u32 U = (u32)(8 * kt + 2 * ks + (grp >> 1));
                u32 offA = (U ^ prx) << 4;
                u32 ah[4], al[4];
                ldm_x4(ah, pbase + offA);
                ldm_x4(al, pbase + 2048 + offA);
                u32 offB = SWZ_UNIT(ks * 16 + rowB0, unitB);
                u32 bh[4], bl[4];
                ldm_x4t(bh, stV + offB);
                ldm_x4t(bl, stV + 16384 + offB);
                #pragma unroll
                for (int tile = 0; tile < 2; ++tile) {
                    mma16816(rhh[tile], ah, bh + 2 * tile);
                    mma16816(rhl[tile], ah, bl + 2 * tile);
                    mma16816(rlh[tile], al, bh + 2 * tile);
                }
            }
            if (kt + 2 < NTILES) {
                copy_kv_tile(st0 + (u32)((kt + 2) % 3) * 32768,
                             g_VHI, g_VLO, (size_t)(b * 16 + kt + 2) << 14, tid);
                CP_COMMIT();
            }
        }
    }

    // ---- result epilogue ----
    #pragma unroll
    for (int tile = 0; tile < 2; ++tile) {
        int col = wn * 16 + tile * 8 + 2 * t;
        int row = q0 + m0 + g;
        *(float2*)&out_res[((size_t)b * TT + row) * DD + col] =
            make_float2(rhh[tile][0] + rhl[tile][0] + rlh[tile][0],
                        rhh[tile][1] + rhl[tile][1] + rlh[tile][1]);
        *(float2*)&out_res[((size_t)b * TT + row + 8) * DD + col] =
            make_float2(rhh[tile][2] + rhl[tile][2] + rlh[tile][2],
                        rhh[tile][3] + rhl[tile][3] + rlh[tile][3]);
    }
}

extern "C" void kernel_launch(void* const* d_in, const int* in_sizes, int n_in,
                              void* d_out, int out_size) {
    const float* key   = (const float*)d_in[0];
    const float* value = (const float*)d_in[1];
    const float* query = (const float*)d_in[2];
    const void*  mask  = d_in[3];
    const float* qmask = (const float*)d_in[4];

    float* out      = (float*)d_out;
    float* out_res  = out;                          // [B, T, D] first (tuple order)
    float* out_attn = out + (size_t)BB * TT * DD;   // [B, T, T] second

    prep_kernel<<<6145, 512>>>(query, key, value, (const unsigned char*)mask);

    cudaFuncSetAttribute(mh_attn_mma10_kernel,
                         cudaFuncAttributeMaxDynamicSharedMemorySize, SM_TOTAL);
    dim3 grid(BB * (TT / QT));   // 2048 CTAs
    mh_attn_mma10_kernel<<<grid, NTHREADS, SM_TOTAL>>>(mask, qmask, out_res, out_attn);
}